// round 11
// baseline (speedup 1.0000x reference)
#include <cuda_runtime.h>
#include <cuda_bf16.h>

// MyAvgPool2D_56444460204139 on GB300 (sm_103a): 1x1/stride-1 avgpool ==
// identity -> out-of-place copy of 51,380,224 fp32 (205.5 MB each way).
//
// Block-geometry trend: 256t/32KB-blocks -> 512t/64KB-blocks improved kernel
// 57.1 -> 56.2us (DRAM 78.7 -> 80.1%): fewer, wider contiguous regions per
// SM => better DRAM row-buffer locality. Final probe: one more doubling,
// 1024 threads x UNROLL=8 = 128KB contiguous per block, 1568 blocks (exact
// cover), 2 resident blocks/SM. Same per-thread MLP=8 (saturated), same
// streaming .cs policy both sides (working set 2x205MB >> 126MB L2).

#define THREADS 1024
#define UNROLL  8   // float4s per thread

__global__ __launch_bounds__(THREADS) void copy_kernel(
    const float4* __restrict__ src, float4* __restrict__ dst)
{
    // Each block owns THREADS*UNROLL = 8192 consecutive float4s (128 KB),
    // per-thread accesses strided by THREADS for full coalescing.
    int base = blockIdx.x * (THREADS * UNROLL) + threadIdx.x;

    float4 v[UNROLL];
    #pragma unroll
    for (int u = 0; u < UNROLL; u++)
        v[u] = __ldcs(&src[base + u * THREADS]);
    #pragma unroll
    for (int u = 0; u < UNROLL; u++)
        __stcs(&dst[base + u * THREADS], v[u]);
}

extern "C" void kernel_launch(void* const* d_in, const int* in_sizes, int n_in,
                              void* d_out, int out_size) {
    const float4* x = (const float4*)d_in[0];
    float4* out = (float4*)d_out;
    // out_size = 51,380,224 floats = 12,845,056 float4s
    // = 1568 blocks * (1024 threads * 8 float4s). Exact cover, no tail.
    int n4 = out_size / 4;
    int per_block = THREADS * UNROLL;
    int blocks = n4 / per_block;  // 1568
    copy_kernel<<<blocks, THREADS>>>(x, out);
}